// round 16
// baseline (speedup 1.0000x reference)
#include <cuda_runtime.h>
#include <cuda_bf16.h>
#include <cstdint>

#define NMAX 100000
#define EMAX 1600000
#define D 128

// ---------------- static device scratch (no allocations allowed) ------------
__device__ int   g_degcur[2 * NMAX];     // [0,NMAX)=deg, [NMAX,2N)=cursor
__device__ int   g_off[NMAX + 1];
__device__ int   g_csr[EMAX];
__device__ float g_mean[(size_t)NMAX * D];
__device__ float g_h0[(size_t)NMAX * D];
__device__ float g_h1[(size_t)NMAX * D];
// packed bf16 hi/lo weight fragments, warp-linear layout:
// index = mat*4096 + ks*512 + nt*32 + lane   (uint4)
__device__ uint4 g_wfrag[6 * 4096];

// ---------------- weight pre-split helper (round-based, prep only) ----------
__device__ __forceinline__ void split_pack2(float a, float b, uint32_t& hi, uint32_t& lo) {
    __nv_bfloat16 ha = __float2bfloat16(a);
    __nv_bfloat16 hb = __float2bfloat16(b);
    float ra = a - __bfloat162float(ha);
    float rb = b - __bfloat162float(hb);
    __nv_bfloat162 H = __halves2bfloat162(ha, hb);
    __nv_bfloat162 L = __halves2bfloat162(__float2bfloat16(ra), __float2bfloat16(rb));
    hi = *reinterpret_cast<uint32_t*>(&H);
    lo = *reinterpret_cast<uint32_t*>(&L);
}

// ---------------- fast truncation split for A operands (hot path) -----------
__device__ __forceinline__ void split_trunc2(float a, float b, uint32_t& hi, uint32_t& lo) {
    uint32_t ua = __float_as_uint(a), ub = __float_as_uint(b);
    hi = __byte_perm(ua, ub, 0x7632);                   // [a.hi16 | b.hi16]
    float ha = __uint_as_float(ua & 0xFFFF0000u);
    float hb = __uint_as_float(ub & 0xFFFF0000u);
    __nv_bfloat162 L = __floats2bfloat162_rn(a - ha, b - hb);
    lo = *reinterpret_cast<uint32_t*>(&L);
}

// ---------------- merged: degree count + weight fragment prep ---------------
__global__ void k_deg_wprep(const int* __restrict__ ei, int E,
                            const float* __restrict__ Wl0, const float* __restrict__ Wr0,
                            const float* __restrict__ Wl, const float* __restrict__ Wr) {
    int t = blockIdx.x * blockDim.x + threadIdx.x;
    if (t < 6 * 4096) {
        int lane = t & 31;
        int nt = (t >> 5) & 15;
        int ks = (t >> 9) & 7;
        int lm = t >> 12;                  // 0..5 = layer*2 + {L,R}
        int g = lane >> 2;
        int tig = lane & 3;
        int n = nt * 8 + g;
        int layer = lm >> 1, mat = lm & 1;
        const float* W;
        if (layer == 0) W = mat ? Wr0 : Wl0;
        else W = (mat ? Wr : Wl) + (size_t)(layer - 1) * D * D;
        int k0 = ks * 16 + tig * 2;
        float w00 = W[(k0 + 0) * D + n];
        float w01 = W[(k0 + 1) * D + n];
        float w80 = W[(k0 + 8) * D + n];
        float w81 = W[(k0 + 9) * D + n];
        uint4 o;
        split_pack2(w00, w01, o.x, o.z);
        split_pack2(w80, w81, o.y, o.w);
        g_wfrag[t] = o;
    }
    if (t < E) atomicAdd(&g_degcur[ei[E + t]], 1);
}

// single-block thread-coarsened exclusive scan of deg -> g_off (+ g_off[n])
__global__ void k_scan(int n) {
    __shared__ int ws[32];
    int tid = threadIdx.x;
    int lane = tid & 31;
    int w = tid >> 5;
    int chunk = (n + 1023) >> 10;
    int beg = tid * chunk; if (beg > n) beg = n;
    int end = beg + chunk; if (end > n) end = n;

    int s = 0;
#pragma unroll 4
    for (int i = beg; i < end; ++i) s += g_degcur[i];

    int incl = s;
#pragma unroll
    for (int d = 1; d < 32; d <<= 1) {
        int u = __shfl_up_sync(0xffffffffu, incl, d);
        if (lane >= d) incl += u;
    }
    if (lane == 31) ws[w] = incl;
    __syncthreads();
    if (w == 0) {
        int v = ws[lane];
        int i2 = v;
#pragma unroll
        for (int d = 1; d < 32; d <<= 1) {
            int u = __shfl_up_sync(0xffffffffu, i2, d);
            if (lane >= d) i2 += u;
        }
        ws[lane] = i2 - v;   // exclusive warp prefix
    }
    __syncthreads();
    int excl = incl - s + ws[w];

    int run = excl;
#pragma unroll 4
    for (int i = beg; i < end; ++i) {
        g_off[i] = run;
        run += g_degcur[i];
    }
    if (tid == 1023) g_off[n] = excl + s;   // total edges
}

__global__ void k_fill(const int* __restrict__ ei, int E) {
    int e = blockIdx.x * blockDim.x + threadIdx.x;
    if (e >= E) return;
    int s = ei[e];
    int d = ei[E + e];
    int pos = atomicAdd(&g_degcur[NMAX + d], 1);
    g_csr[g_off[d] + pos] = s;
}

// ---------------- mean aggregation: 1 warp per node (fp32, 4-wide) ----------
__global__ void k_agg(const float* __restrict__ h, int N) {
    int warp = (blockIdx.x * blockDim.x + threadIdx.x) >> 5;
    int lane = threadIdx.x & 31;
    if (warp >= N) return;
    int beg = g_off[warp];
    int end = g_off[warp + 1];
    const float4* hv = (const float4*)h;
    float4 acc = make_float4(0.f, 0.f, 0.f, 0.f);
    int e = beg;
    for (; e + 4 <= end; e += 4) {
        int s0 = g_csr[e + 0], s1 = g_csr[e + 1], s2 = g_csr[e + 2], s3 = g_csr[e + 3];
        float4 v0 = hv[(size_t)s0 * 32 + lane];
        float4 v1 = hv[(size_t)s1 * 32 + lane];
        float4 v2 = hv[(size_t)s2 * 32 + lane];
        float4 v3 = hv[(size_t)s3 * 32 + lane];
        acc.x += (v0.x + v1.x) + (v2.x + v3.x);
        acc.y += (v0.y + v1.y) + (v2.y + v3.y);
        acc.z += (v0.z + v1.z) + (v2.z + v3.z);
        acc.w += (v0.w + v1.w) + (v2.w + v3.w);
    }
    for (; e < end; ++e) {
        int s = g_csr[e];
        float4 v = hv[(size_t)s * 32 + lane];
        acc.x += v.x; acc.y += v.y; acc.z += v.z; acc.w += v.w;
    }
    float scale = (end > beg) ? 1.f / (float)(end - beg) : 0.f;
    acc.x *= scale; acc.y *= scale; acc.z *= scale; acc.w *= scale;
    ((float4*)g_mean)[(size_t)warp * 32 + lane] = acc;
}

// ---------------- GEMM (bf16x3, SMEM-staged weights) + bias + LN + ReLU -----
__device__ __forceinline__ void mma16816(float c[4], const uint32_t a[4],
                                         uint32_t b0, uint32_t b1) {
    asm volatile(
        "mma.sync.aligned.m16n8k16.row.col.f32.bf16.bf16.f32 "
        "{%0,%1,%2,%3}, {%4,%5,%6,%7}, {%8,%9}, {%0,%1,%2,%3};\n"
        : "+f"(c[0]), "+f"(c[1]), "+f"(c[2]), "+f"(c[3])
        : "r"(a[0]), "r"(a[1]), "r"(a[2]), "r"(a[3]), "r"(b0), "r"(b1));
}

#define SW_BYTES (4096 * 16)   // one matrix of fragments = 64KB

// one GEMM phase: acc += bf16x3( A_src rows ) @ W(staged in sw)
__device__ __forceinline__ void gemm_phase(float acc[16][4],
                                           const uint4* __restrict__ sw,
                                           const float* __restrict__ rowA,
                                           const float* __restrict__ rowB,
                                           int tig, int lane) {
#pragma unroll 2
    for (int ks = 0; ks < 8; ++ks) {
        int k0 = ks * 16 + tig * 2;
        float2 a0 = *(const float2*)(rowA + k0);
        float2 a1 = *(const float2*)(rowB + k0);
        float2 a2 = *(const float2*)(rowA + k0 + 8);
        float2 a3 = *(const float2*)(rowB + k0 + 8);

        uint32_t Ahi[4], Alo[4];
        split_trunc2(a0.x, a0.y, Ahi[0], Alo[0]);
        split_trunc2(a1.x, a1.y, Ahi[1], Alo[1]);
        split_trunc2(a2.x, a2.y, Ahi[2], Alo[2]);
        split_trunc2(a3.x, a3.y, Ahi[3], Alo[3]);

        const uint4* p = sw + ks * 512 + lane;
#pragma unroll
        for (int nt = 0; nt < 16; ++nt) {
            uint4 f = p[nt * 32];              // LDS.128, conflict-free
            mma16816(acc[nt], Ahi, f.x, f.y);  // hi * Whi
            mma16816(acc[nt], Alo, f.x, f.y);  // lo * Whi
            mma16816(acc[nt], Ahi, f.z, f.w);  // hi * Wlo
        }
    }
}

__global__ void __launch_bounds__(256)
k_gemm_ln(const float* __restrict__ h, int layer,
          const float* __restrict__ bias, const float* __restrict__ gamma,
          const float* __restrict__ beta, float* __restrict__ out, int N) {
    extern __shared__ uint4 sw[];   // 4096 uint4 (one weight matrix)
    int tid = threadIdx.x;
    int warp = tid >> 5;
    int lane = tid & 31;
    int g = lane >> 2;
    int tig = lane & 3;
    int rowbase = blockIdx.x * 128 + warp * 16;
    int rA = rowbase + g;
    int rB = rA + 8;
    int rAc = min(rA, N - 1);
    int rBc = min(rB, N - 1);

    float acc[16][4];
#pragma unroll
    for (int i = 0; i < 16; i++) {
        acc[i][0] = 0.f; acc[i][1] = 0.f; acc[i][2] = 0.f; acc[i][3] = 0.f;
    }

    // ---- phase L: stage Wl fragments, mean @ Wl ----
    {
        const uint4* wsrc = g_wfrag + (size_t)(layer * 2 + 0) * 4096;
#pragma unroll
        for (int i = 0; i < 16; ++i) sw[i * 256 + tid] = wsrc[i * 256 + tid];
        __syncthreads();
        gemm_phase(acc, sw, g_mean + (size_t)rAc * D, g_mean + (size_t)rBc * D, tig, lane);
        __syncthreads();
    }
    // ---- phase R: stage Wr fragments, h @ Wr ----
    {
        const uint4* wsrc = g_wfrag + (size_t)(layer * 2 + 1) * 4096;
#pragma unroll
        for (int i = 0; i < 16; ++i) sw[i * 256 + tid] = wsrc[i * 256 + tid];
        __syncthreads();
        gemm_phase(acc, sw, h + (size_t)rAc * D, h + (size_t)rBc * D, tig, lane);
    }

    // epilogue: + bias, LayerNorm over the 128-wide row (4 lanes per row), ReLU
    float sA = 0.f, qA = 0.f, sB = 0.f, qB = 0.f;
#pragma unroll
    for (int nt = 0; nt < 16; ++nt) {
        int col = nt * 8 + tig * 2;
        float2 bv = *(const float2*)(bias + col);
        acc[nt][0] += bv.x; acc[nt][1] += bv.y;
        acc[nt][2] += bv.x; acc[nt][3] += bv.y;
        sA += acc[nt][0] + acc[nt][1];
        qA += acc[nt][0] * acc[nt][0] + acc[nt][1] * acc[nt][1];
        sB += acc[nt][2] + acc[nt][3];
        qB += acc[nt][2] * acc[nt][2] + acc[nt][3] * acc[nt][3];
    }
#pragma unroll
    for (int m = 1; m <= 2; m <<= 1) {
        sA += __shfl_xor_sync(0xffffffff, sA, m);
        qA += __shfl_xor_sync(0xffffffff, qA, m);
        sB += __shfl_xor_sync(0xffffffff, sB, m);
        qB += __shfl_xor_sync(0xffffffff, qB, m);
    }
    const float inv = 1.f / 128.f;
    float muA = sA * inv;
    float vA = fmaxf(qA * inv - muA * muA, 0.f);
    float rsA = rsqrtf(vA + 1e-5f);
    float muB = sB * inv;
    float vB = fmaxf(qB * inv - muB * muB, 0.f);
    float rsB = rsqrtf(vB + 1e-5f);

#pragma unroll
    for (int nt = 0; nt < 16; ++nt) {
        int col = nt * 8 + tig * 2;
        float2 gv = *(const float2*)(gamma + col);
        float2 bv = *(const float2*)(beta + col);
        if (rA < N) {
            float2 o;
            o.x = fmaxf(0.f, (acc[nt][0] - muA) * rsA * gv.x + bv.x);
            o.y = fmaxf(0.f, (acc[nt][1] - muA) * rsA * gv.y + bv.y);
            *(float2*)(out + (size_t)rA * D + col) = o;
        }
        if (rB < N) {
            float2 o;
            o.x = fmaxf(0.f, (acc[nt][2] - muB) * rsB * gv.x + bv.x);
            o.y = fmaxf(0.f, (acc[nt][3] - muB) * rsB * gv.y + bv.y);
            *(float2*)(out + (size_t)rB * D + col) = o;
        }
    }
}

// ---------------- launch ----------------------------------------------------
extern "C" void kernel_launch(void* const* d_in, const int* in_sizes, int n_in,
                              void* d_out, int out_size) {
    const float* x   = (const float*)d_in[0];
    const int*   ei  = (const int*)d_in[1];
    const float* Wl0 = (const float*)d_in[2];
    const float* bl0 = (const float*)d_in[3];
    const float* Wr0 = (const float*)d_in[4];
    const float* g0  = (const float*)d_in[5];
    const float* be0 = (const float*)d_in[6];
    const float* Wl  = (const float*)d_in[7];
    const float* bl  = (const float*)d_in[8];
    const float* Wr  = (const float*)d_in[9];
    const float* gg  = (const float*)d_in[10];
    const float* be  = (const float*)d_in[11];
    float* out = (float*)d_out;

    int N = in_sizes[0] / D;
    int E = in_sizes[1] / 2;

    float* h0;  cudaGetSymbolAddress((void**)&h0, g_h0);
    float* h1;  cudaGetSymbolAddress((void**)&h1, g_h1);
    int* degcur; cudaGetSymbolAddress((void**)&degcur, g_degcur);

    static int smem_set = 0;
    if (!smem_set) {
        cudaFuncSetAttribute(k_gemm_ln, cudaFuncAttributeMaxDynamicSharedMemorySize,
                             SW_BYTES);
        smem_set = 1;
    }

    // zero deg+cursor (memset node, not a kernel launch)
    cudaMemsetAsync(degcur, 0, 2 * NMAX * sizeof(int));

    // CSR build + weight prep
    k_deg_wprep<<<(E + 255) / 256, 256>>>(ei, E, Wl0, Wr0, Wl, Wr);  // launch 1
    k_scan<<<1, 1024>>>(N);                                          // launch 2
    k_fill<<<(E + 255) / 256, 256>>>(ei, E);                         // launch 3

    int agg_blocks = (N + 7) / 8;       // 1 warp per node
    int gemm_blocks = (N + 127) / 128;  // 128 rows per block

    // layer 0
    k_agg<<<agg_blocks, 256>>>(x, N);                                // launch 4 (profiled)
    k_gemm_ln<<<gemm_blocks, 256, SW_BYTES>>>(x, 0, bl0, g0, be0, h0, N);
    // layer 1
    k_agg<<<agg_blocks, 256>>>(h0, N);
    k_gemm_ln<<<gemm_blocks, 256, SW_BYTES>>>(h0, 1, bl, gg, be, h1, N);
    // layer 2
    k_agg<<<agg_blocks, 256>>>(h1, N);
    k_gemm_ln<<<gemm_blocks, 256, SW_BYTES>>>(h1, 2, bl + D, gg + D, be + D, out, N);
}

// round 17
// speedup vs baseline: 1.1190x; 1.1190x over previous
#include <cuda_runtime.h>
#include <cuda_bf16.h>
#include <cstdint>

#define NMAX 100000
#define EMAX 1600000
#define D 128

// ---------------- static device scratch (no allocations allowed) ------------
__device__ int   g_degcur[2 * NMAX];     // [0,NMAX)=deg, [NMAX,2N)=cursor
__device__ int   g_off[NMAX + 1];
__device__ int   g_csr[EMAX];
__device__ float g_mean[(size_t)NMAX * D];
__device__ float g_h0[(size_t)NMAX * D];
__device__ float g_h1[(size_t)NMAX * D];
// packed bf16 hi/lo weight fragments, warp-linear layout:
// index = mat*4096 + ks*512 + nt*32 + lane   (uint4)
__device__ uint4 g_wfrag[6 * 4096];

// ---------------- weight pre-split helper (round-based, prep only) ----------
__device__ __forceinline__ void split_pack2(float a, float b, uint32_t& hi, uint32_t& lo) {
    __nv_bfloat16 ha = __float2bfloat16(a);
    __nv_bfloat16 hb = __float2bfloat16(b);
    float ra = a - __bfloat162float(ha);
    float rb = b - __bfloat162float(hb);
    __nv_bfloat162 H = __halves2bfloat162(ha, hb);
    __nv_bfloat162 L = __halves2bfloat162(__float2bfloat16(ra), __float2bfloat16(rb));
    hi = *reinterpret_cast<uint32_t*>(&H);
    lo = *reinterpret_cast<uint32_t*>(&L);
}

// ---------------- fast truncation split for A operands (hot path) -----------
__device__ __forceinline__ void split_trunc2(float a, float b, uint32_t& hi, uint32_t& lo) {
    uint32_t ua = __float_as_uint(a), ub = __float_as_uint(b);
    hi = __byte_perm(ua, ub, 0x7632);                   // [a.hi16 | b.hi16]
    float ha = __uint_as_float(ua & 0xFFFF0000u);
    float hb = __uint_as_float(ub & 0xFFFF0000u);
    __nv_bfloat162 L = __floats2bfloat162_rn(a - ha, b - hb);
    lo = *reinterpret_cast<uint32_t*>(&L);
}

// ---------------- merged: degree count + weight fragment prep ---------------
__global__ void k_deg_wprep(const int* __restrict__ ei, int E,
                            const float* __restrict__ Wl0, const float* __restrict__ Wr0,
                            const float* __restrict__ Wl, const float* __restrict__ Wr) {
    int t = blockIdx.x * blockDim.x + threadIdx.x;
    if (t < 6 * 4096) {
        int lane = t & 31;
        int nt = (t >> 5) & 15;
        int ks = (t >> 9) & 7;
        int lm = t >> 12;                  // 0..5 = layer*2 + {L,R}
        int g = lane >> 2;
        int tig = lane & 3;
        int n = nt * 8 + g;
        int layer = lm >> 1, mat = lm & 1;
        const float* W;
        if (layer == 0) W = mat ? Wr0 : Wl0;
        else W = (mat ? Wr : Wl) + (size_t)(layer - 1) * D * D;
        int k0 = ks * 16 + tig * 2;
        float w00 = W[(k0 + 0) * D + n];
        float w01 = W[(k0 + 1) * D + n];
        float w80 = W[(k0 + 8) * D + n];
        float w81 = W[(k0 + 9) * D + n];
        uint4 o;
        split_pack2(w00, w01, o.x, o.z);
        split_pack2(w80, w81, o.y, o.w);
        g_wfrag[t] = o;
    }
    if (t < E) atomicAdd(&g_degcur[ei[E + t]], 1);
}

// single-block thread-coarsened exclusive scan of deg -> g_off (+ g_off[n])
__global__ void k_scan(int n) {
    __shared__ int ws[32];
    int tid = threadIdx.x;
    int lane = tid & 31;
    int w = tid >> 5;
    int chunk = (n + 1023) >> 10;
    int beg = tid * chunk; if (beg > n) beg = n;
    int end = beg + chunk; if (end > n) end = n;

    int s = 0;
#pragma unroll 4
    for (int i = beg; i < end; ++i) s += g_degcur[i];

    int incl = s;
#pragma unroll
    for (int d = 1; d < 32; d <<= 1) {
        int u = __shfl_up_sync(0xffffffffu, incl, d);
        if (lane >= d) incl += u;
    }
    if (lane == 31) ws[w] = incl;
    __syncthreads();
    if (w == 0) {
        int v = ws[lane];
        int i2 = v;
#pragma unroll
        for (int d = 1; d < 32; d <<= 1) {
            int u = __shfl_up_sync(0xffffffffu, i2, d);
            if (lane >= d) i2 += u;
        }
        ws[lane] = i2 - v;   // exclusive warp prefix
    }
    __syncthreads();
    int excl = incl - s + ws[w];

    int run = excl;
#pragma unroll 4
    for (int i = beg; i < end; ++i) {
        g_off[i] = run;
        run += g_degcur[i];
    }
    if (tid == 1023) g_off[n] = excl + s;   // total edges
}

__global__ void k_fill(const int* __restrict__ ei, int E) {
    int e = blockIdx.x * blockDim.x + threadIdx.x;
    if (e >= E) return;
    int s = ei[e];
    int d = ei[E + e];
    int pos = atomicAdd(&g_degcur[NMAX + d], 1);
    g_csr[g_off[d] + pos] = s;
}

// ---------------- mean aggregation: 1 warp per node (fp32, 4-wide) ----------
__global__ void k_agg(const float* __restrict__ h, int N) {
    int warp = (blockIdx.x * blockDim.x + threadIdx.x) >> 5;
    int lane = threadIdx.x & 31;
    if (warp >= N) return;
    int beg = g_off[warp];
    int end = g_off[warp + 1];
    const float4* hv = (const float4*)h;
    float4 acc = make_float4(0.f, 0.f, 0.f, 0.f);
    int e = beg;
    for (; e + 4 <= end; e += 4) {
        int s0 = g_csr[e + 0], s1 = g_csr[e + 1], s2 = g_csr[e + 2], s3 = g_csr[e + 3];
        float4 v0 = hv[(size_t)s0 * 32 + lane];
        float4 v1 = hv[(size_t)s1 * 32 + lane];
        float4 v2 = hv[(size_t)s2 * 32 + lane];
        float4 v3 = hv[(size_t)s3 * 32 + lane];
        acc.x += (v0.x + v1.x) + (v2.x + v3.x);
        acc.y += (v0.y + v1.y) + (v2.y + v3.y);
        acc.z += (v0.z + v1.z) + (v2.z + v3.z);
        acc.w += (v0.w + v1.w) + (v2.w + v3.w);
    }
    for (; e < end; ++e) {
        int s = g_csr[e];
        float4 v = hv[(size_t)s * 32 + lane];
        acc.x += v.x; acc.y += v.y; acc.z += v.z; acc.w += v.w;
    }
    float scale = (end > beg) ? 1.f / (float)(end - beg) : 0.f;
    acc.x *= scale; acc.y *= scale; acc.z *= scale; acc.w *= scale;
    ((float4*)g_mean)[(size_t)warp * 32 + lane] = acc;
}

// ---------------- GEMM (bf16x3, SMEM-staged weights) + bias + LN + ReLU -----
__device__ __forceinline__ void mma16816(float c[4], const uint32_t a[4],
                                         uint32_t b0, uint32_t b1) {
    asm volatile(
        "mma.sync.aligned.m16n8k16.row.col.f32.bf16.bf16.f32 "
        "{%0,%1,%2,%3}, {%4,%5,%6,%7}, {%8,%9}, {%0,%1,%2,%3};\n"
        : "+f"(c[0]), "+f"(c[1]), "+f"(c[2]), "+f"(c[3])
        : "r"(a[0]), "r"(a[1]), "r"(a[2]), "r"(a[3]), "r"(b0), "r"(b1));
}

#define SW_BYTES (4096 * 16)   // one matrix of fragments = 64KB

// one GEMM phase: acc += bf16x3( A_src rows ) @ W(staged in sw)
__device__ __forceinline__ void gemm_phase(float acc[16][4],
                                           const uint4* __restrict__ sw,
                                           const float* __restrict__ rowA,
                                           const float* __restrict__ rowB,
                                           int tig, int lane) {
#pragma unroll 1
    for (int ks = 0; ks < 8; ++ks) {
        int k0 = ks * 16 + tig * 2;
        float2 a0 = *(const float2*)(rowA + k0);
        float2 a1 = *(const float2*)(rowB + k0);
        float2 a2 = *(const float2*)(rowA + k0 + 8);
        float2 a3 = *(const float2*)(rowB + k0 + 8);

        uint32_t Ahi[4], Alo[4];
        split_trunc2(a0.x, a0.y, Ahi[0], Alo[0]);
        split_trunc2(a1.x, a1.y, Ahi[1], Alo[1]);
        split_trunc2(a2.x, a2.y, Ahi[2], Alo[2]);
        split_trunc2(a3.x, a3.y, Ahi[3], Alo[3]);

        const uint4* p = sw + ks * 512 + lane;
#pragma unroll
        for (int nt = 0; nt < 16; ++nt) {
            uint4 f = p[nt * 32];              // LDS.128, conflict-free
            mma16816(acc[nt], Ahi, f.x, f.y);  // hi * Whi
            mma16816(acc[nt], Alo, f.x, f.y);  // lo * Whi
            mma16816(acc[nt], Ahi, f.z, f.w);  // hi * Wlo
        }
    }
}

__global__ void __launch_bounds__(256)
k_gemm_ln(const float* __restrict__ h, int layer,
          const float* __restrict__ bias, const float* __restrict__ gamma,
          const float* __restrict__ beta, float* __restrict__ out, int N) {
    extern __shared__ uint4 sw[];   // 4096 uint4 (one weight matrix)
    int tid = threadIdx.x;
    int warp = tid >> 5;
    int lane = tid & 31;
    int g = lane >> 2;
    int tig = lane & 3;
    int rowbase = blockIdx.x * 128 + warp * 16;
    int rA = rowbase + g;
    int rB = rA + 8;
    int rAc = min(rA, N - 1);
    int rBc = min(rB, N - 1);

    float acc[16][4];
#pragma unroll
    for (int i = 0; i < 16; i++) {
        acc[i][0] = 0.f; acc[i][1] = 0.f; acc[i][2] = 0.f; acc[i][3] = 0.f;
    }

    // ---- phase L: stage Wl fragments, mean @ Wl ----
    {
        const uint4* wsrc = g_wfrag + (size_t)(layer * 2 + 0) * 4096;
#pragma unroll
        for (int i = 0; i < 16; ++i) sw[i * 256 + tid] = wsrc[i * 256 + tid];
        __syncthreads();
        gemm_phase(acc, sw, g_mean + (size_t)rAc * D, g_mean + (size_t)rBc * D, tig, lane);
        __syncthreads();
    }
    // ---- phase R: stage Wr fragments, h @ Wr ----
    {
        const uint4* wsrc = g_wfrag + (size_t)(layer * 2 + 1) * 4096;
#pragma unroll
        for (int i = 0; i < 16; ++i) sw[i * 256 + tid] = wsrc[i * 256 + tid];
        __syncthreads();
        gemm_phase(acc, sw, h + (size_t)rAc * D, h + (size_t)rBc * D, tig, lane);
    }

    // epilogue: + bias, LayerNorm over the 128-wide row (4 lanes per row), ReLU
    float sA = 0.f, qA = 0.f, sB = 0.f, qB = 0.f;
#pragma unroll
    for (int nt = 0; nt < 16; ++nt) {
        int col = nt * 8 + tig * 2;
        float2 bv = *(const float2*)(bias + col);
        acc[nt][0] += bv.x; acc[nt][1] += bv.y;
        acc[nt][2] += bv.x; acc[nt][3] += bv.y;
        sA += acc[nt][0] + acc[nt][1];
        qA += acc[nt][0] * acc[nt][0] + acc[nt][1] * acc[nt][1];
        sB += acc[nt][2] + acc[nt][3];
        qB += acc[nt][2] * acc[nt][2] + acc[nt][3] * acc[nt][3];
    }
#pragma unroll
    for (int m = 1; m <= 2; m <<= 1) {
        sA += __shfl_xor_sync(0xffffffff, sA, m);
        qA += __shfl_xor_sync(0xffffffff, qA, m);
        sB += __shfl_xor_sync(0xffffffff, sB, m);
        qB += __shfl_xor_sync(0xffffffff, qB, m);
    }
    const float inv = 1.f / 128.f;
    float muA = sA * inv;
    float vA = fmaxf(qA * inv - muA * muA, 0.f);
    float rsA = rsqrtf(vA + 1e-5f);
    float muB = sB * inv;
    float vB = fmaxf(qB * inv - muB * muB, 0.f);
    float rsB = rsqrtf(vB + 1e-5f);

#pragma unroll
    for (int nt = 0; nt < 16; ++nt) {
        int col = nt * 8 + tig * 2;
        float2 gv = *(const float2*)(gamma + col);
        float2 bv = *(const float2*)(beta + col);
        if (rA < N) {
            float2 o;
            o.x = fmaxf(0.f, (acc[nt][0] - muA) * rsA * gv.x + bv.x);
            o.y = fmaxf(0.f, (acc[nt][1] - muA) * rsA * gv.y + bv.y);
            *(float2*)(out + (size_t)rA * D + col) = o;
        }
        if (rB < N) {
            float2 o;
            o.x = fmaxf(0.f, (acc[nt][2] - muB) * rsB * gv.x + bv.x);
            o.y = fmaxf(0.f, (acc[nt][3] - muB) * rsB * gv.y + bv.y);
            *(float2*)(out + (size_t)rB * D + col) = o;
        }
    }
}

// ---------------- launch ----------------------------------------------------
extern "C" void kernel_launch(void* const* d_in, const int* in_sizes, int n_in,
                              void* d_out, int out_size) {
    const float* x   = (const float*)d_in[0];
    const int*   ei  = (const int*)d_in[1];
    const float* Wl0 = (const float*)d_in[2];
    const float* bl0 = (const float*)d_in[3];
    const float* Wr0 = (const float*)d_in[4];
    const float* g0  = (const float*)d_in[5];
    const float* be0 = (const float*)d_in[6];
    const float* Wl  = (const float*)d_in[7];
    const float* bl  = (const float*)d_in[8];
    const float* Wr  = (const float*)d_in[9];
    const float* gg  = (const float*)d_in[10];
    const float* be  = (const float*)d_in[11];
    float* out = (float*)d_out;

    int N = in_sizes[0] / D;
    int E = in_sizes[1] / 2;

    float* h0;  cudaGetSymbolAddress((void**)&h0, g_h0);
    float* h1;  cudaGetSymbolAddress((void**)&h1, g_h1);
    int* degcur; cudaGetSymbolAddress((void**)&degcur, g_degcur);

    static int smem_set = 0;
    if (!smem_set) {
        cudaFuncSetAttribute(k_gemm_ln, cudaFuncAttributeMaxDynamicSharedMemorySize,
                             SW_BYTES);
        smem_set = 1;
    }

    // zero deg+cursor (memset node, not a kernel launch)
    cudaMemsetAsync(degcur, 0, 2 * NMAX * sizeof(int));

    // CSR build + weight prep
    k_deg_wprep<<<(E + 255) / 256, 256>>>(ei, E, Wl0, Wr0, Wl, Wr);  // launch 1
    k_scan<<<1, 1024>>>(N);                                          // launch 2
    k_fill<<<(E + 255) / 256, 256>>>(ei, E);                         // launch 3

    int agg_blocks = (N + 7) / 8;       // 1 warp per node
    int gemm_blocks = (N + 127) / 128;  // 128 rows per block

    // layer 0
    k_agg<<<agg_blocks, 256>>>(x, N);                                // launch 4 (profiled)
    k_gemm_ln<<<gemm_blocks, 256, SW_BYTES>>>(x, 0, bl0, g0, be0, h0, N);
    // layer 1
    k_agg<<<agg_blocks, 256>>>(h0, N);
    k_gemm_ln<<<gemm_blocks, 256, SW_BYTES>>>(h0, 1, bl, gg, be, h1, N);
    // layer 2
    k_agg<<<agg_blocks, 256>>>(h1, N);
    k_gemm_ln<<<gemm_blocks, 256, SW_BYTES>>>(h1, 2, bl + D, gg + D, be + D, out, N);
}